// round 16
// baseline (speedup 1.0000x reference)
#include <cuda_runtime.h>

#define C    256
#define CH   128
#define HWn  262144
#define HW4  65536
#define TOT4 16777216          // C * HW4 flat float4 count
#define EPS  1e-5f

#define TP     32
#define TP4    8
#define TILE_F  (C * TP)       // 8192 floats = 32 KB
#define NTILES  (HWn / TP)     // 8192 tiles
#define MAXCTA  512

__device__ float d_pA[2 * MAXCTA];     // per-CTA partial sums (2 channel spans each)
__device__ int   d_pAch[2 * MAXCTA];   // channel id per entry (-1 = unused)
__device__ float d_g[C];
__device__ float d_v[C];
__device__ float d_b0;
__device__ unsigned d_doneA;           // phase-A completion count
__device__ int d_ctrB;                 // phase-B steal counter
__device__ unsigned d_doneB;           // phase-B completion count
__device__ volatile unsigned d_flag;   // scalars ready

__device__ __forceinline__ void k3_prefetch(const float4* __restrict__ x4,
                                            float* buf, int tile, int t) {
    if (tile < NTILES) {
        unsigned dst_base = (unsigned)__cvta_generic_to_shared(buf);
        const int base4 = tile * TP4;
#pragma unroll
        for (int j = 0; j < 8; j++) {
            int i4 = t + j * 256;
            int c = i4 >> 3, p4 = i4 & 7;
            const float4* src = x4 + (size_t)c * HW4 + base4 + p4;
            unsigned dst = dst_base + i4 * 16;
            asm volatile("cp.async.cg.shared.global [%0], [%1], 16;\n" :: "r"(dst), "l"(src));
        }
    }
    asm volatile("cp.async.commit_group;\n");
}

// block-reduce helper over red[256]; result in red[0]
__device__ __forceinline__ void blk_sum(float* red, int t) {
    __syncthreads();
    for (int off = 128; off > 0; off >>= 1) {
        if (t < off) red[t] += red[t + off];
        __syncthreads();
    }
}

__global__ __launch_bounds__(256, 3)
void psa_one(const float4* __restrict__ x4, float4* __restrict__ out4,
             int ncta, int Q,
             const float* __restrict__ cv1w, const float* __restrict__ cv1b,
             const float* __restrict__ cv3w, const float* __restrict__ cv3b,
             const float* __restrict__ lng,  const float* __restrict__ lnb,
             const float* __restrict__ sp1w, const float* __restrict__ sp1b,
             const float* __restrict__ sp2w, const float* __restrict__ sp2b) {
    extern __shared__ float sm[];
    float* buf0 = sm;                    // TILE_F
    float* buf1 = sm + TILE_F;           // TILE_F
    float* sv   = sm + 2 * TILE_F;       // C   (phase-A scalar scratch S)
    float* sg   = sv + C;                // C   (phase-A scalar scratch l1)
    float* red  = sg + C;                // 256 (reductions / dot partials)
    float* sy   = red + 256;             // TP
    __shared__ int ssteal[3];
    __shared__ unsigned srank;

    const int t = threadIdx.x;
    const int cta = blockIdx.x;

    // ============ Phase A: static contiguous slice, register streaming ============
    {
        const int lo = cta * Q;
        const int hi = min(lo + Q, TOT4);
        float s0 = 0.f, s1 = 0.f;
        int c0 = -1, c1 = -1;
        if (lo < hi) {
            c0 = lo >> 16;
            const int b = min(hi, (c0 + 1) << 16);
            // ---- span 0: [lo, b), channel c0 ----
            {
                float s = 0.f;
                int i4 = lo + t;
                for (; i4 < b - 1792; i4 += 2048) {
                    float4 u[8];
#pragma unroll
                    for (int j = 0; j < 8; j++) u[j] = x4[i4 + j * 256];
#pragma unroll
                    for (int j = 0; j < 8; j++) s += (u[j].x + u[j].y) + (u[j].z + u[j].w);
                }
                for (; i4 < b; i4 += 256) {
                    float4 u = x4[i4];
                    s += (u.x + u.y) + (u.z + u.w);
                }
                red[t] = s;
                blk_sum(red, t);
                s0 = red[0];
                __syncthreads();
            }
            // ---- span 1: [b, hi), channel c0+1 (if any) ----
            if (b < hi) {
                c1 = c0 + 1;
                float s = 0.f;
                int i4 = b + t;
                for (; i4 < hi - 1792; i4 += 2048) {
                    float4 u[8];
#pragma unroll
                    for (int j = 0; j < 8; j++) u[j] = x4[i4 + j * 256];
#pragma unroll
                    for (int j = 0; j < 8; j++) s += (u[j].x + u[j].y) + (u[j].z + u[j].w);
                }
                for (; i4 < hi; i4 += 256) {
                    float4 u = x4[i4];
                    s += (u.x + u.y) + (u.z + u.w);
                }
                red[t] = s;
                blk_sum(red, t);
                s1 = red[0];
                __syncthreads();
            }
        }
        if (t == 0) {
            d_pA[2 * cta]     = s0;  d_pAch[2 * cta]     = c0;
            d_pA[2 * cta + 1] = s1;  d_pAch[2 * cta + 1] = c1;
        }
    }

    // ---- phase-A completion rank ----
    __threadfence();
    if (t == 0) srank = atomicAdd(&d_doneA, 1u);
    __syncthreads();
    const bool isScalar = (srank == (unsigned)(ncta - 1));

    // ---- steal + prefetch first two phase-B tiles (overlaps stragglers/scalars) ----
    if (t == 0) {
        ssteal[0] = atomicAdd(&d_ctrB, 1);
        ssteal[1] = atomicAdd(&d_ctrB, 1);
    }
    __syncthreads();
    int cur_t = ssteal[0], nxt_t = ssteal[1];
    k3_prefetch(x4, buf0, cur_t, t);
    k3_prefetch(x4, buf1, nxt_t, t);

    // ============ Scalars (last-finishing CTA) / poll (others) ============
    if (isScalar) {
        float* S  = sv;   // scratch before sv/sg get their real contents
        float* l1 = sg;
        // gather S[c] from the ~4 CTA ranges intersecting channel c (fixed order)
        {
            const int c = t;
            int k_lo = (c << 16) / Q - 1;  if (k_lo < 0) k_lo = 0;
            int k_hi = ((c + 1) << 16) / Q + 1;  if (k_hi > ncta - 1) k_hi = ncta - 1;
            float ss = 0.f;
            for (int k = k_lo; k <= k_hi; k++) {
                if (d_pAch[2 * k] == c)     ss += d_pA[2 * k];
                if (d_pAch[2 * k + 1] == c) ss += d_pA[2 * k + 1];
            }
            S[c] = ss;
        }
        __syncthreads();
        if (t < CH) {
            float a = 0.f;
            for (int cc = 0; cc < C; cc++) a += cv1w[t * C + cc] * S[cc];
            l1[t] = a + (float)HWn * cv1b[t];
        } else {
            const int u = t - CH;
            float a = 0.f;
            for (int cc = 0; cc < C; cc++) a += sp2w[u * C + cc] * S[cc];
            l1[t] = a * (1.f / (float)HWn) + sp2b[u];
        }
        __syncthreads();
        float zv = cv3b[t];
        for (int cc = 0; cc < CH; cc++) zv += cv3w[t * CH + cc] * l1[cc];
        red[t] = zv;
        blk_sum(red, t);
        const float mu = red[0] * (1.f / (float)C);
        __syncthreads();
        red[t] = zv * zv;
        blk_sum(red, t);
        const float var = red[0] * (1.f / (float)C) - mu * mu;
        __syncthreads();
        const float zn = (zv - mu) * rsqrtf(var + EPS) * lng[t] + lnb[t];
        d_g[t] = 1.f / (1.f + expf(-zn));

        red[t] = (t < CH) ? l1[CH + t] : -1e30f;
        __syncthreads();
        for (int off = 128; off > 0; off >>= 1) {
            if (t < off) red[t] = fmaxf(red[t], red[t + off]);
            __syncthreads();
        }
        const float mx = red[0];
        __syncthreads();
        red[t] = (t < CH) ? expf(l1[CH + t] - mx) : 0.f;
        blk_sum(red, t);
        const float denom = red[0];
        __syncthreads();
        if (t < CH) l1[CH + t] = expf(l1[CH + t] - mx) / denom;   // wsm
        __syncthreads();
        {
            float vv = 0.f;
            for (int c_ = 0; c_ < CH; c_++) vv += l1[CH + c_] * sp1w[c_ * C + t];
            d_v[t] = vv;
        }
        if (t == 0) {
            float bb = 0.f;
            for (int c_ = 0; c_ < CH; c_++) bb += l1[CH + c_] * sp1b[c_];
            d_b0 = bb;
        }
        __threadfence();
        __syncthreads();
        if (t == 0) d_flag = 1u;
    } else {
        if (t == 0) {
            while (d_flag == 0u) __nanosleep(200);
        }
        __syncthreads();
        __threadfence();
    }

    sv[t] = d_v[t];
    sg[t] = d_g[t];
    const float b0 = d_b0;

    // ============ Phase B: champion work-stealing pipeline ============
    int i = 0;
    while (cur_t < NTILES) {
        float* cur = (i & 1) ? buf1 : buf0;
        float4* cur4 = (float4*)cur;

        if (t == 0) ssteal[2] = atomicAdd(&d_ctrB, 1);
        asm volatile("cp.async.wait_group 1;\n");
        __syncthreads();
        const int nn = ssteal[2];

        {
            const int p = t & 31, q = t >> 5;
            float acc = 0.f;
            const float* tp_ = cur + (q * 32) * TP + p;
            const float* vp  = sv + q * 32;
#pragma unroll
            for (int c = 0; c < 32; c++) acc += vp[c] * tp_[c * TP];
            red[q * TP + p] = acc;
        }
        __syncthreads();
        if (t < TP) {
            float yb = b0;
#pragma unroll
            for (int q = 0; q < 8; q++) yb += red[q * TP + t];
            sy[t] = 1.f / (1.f + expf(-yb));
        }
        __syncthreads();

        const int base4 = cur_t * TP4;
#pragma unroll
        for (int j = 0; j < 8; j++) {
            int i4 = t + j * 256;
            int c = i4 >> 3, p4 = i4 & 7;
            float4 xv = cur4[i4];
            const float gv = sg[c];
            const int p = p4 * 4;
            float4 o;
            o.x = (gv + sy[p + 0]) * xv.x;
            o.y = (gv + sy[p + 1]) * xv.y;
            o.z = (gv + sy[p + 2]) * xv.z;
            o.w = (gv + sy[p + 3]) * xv.w;
            out4[(size_t)c * HW4 + base4 + p4] = o;
        }
        __syncthreads();
        k3_prefetch(x4, cur, nn, t);
        cur_t = nxt_t;
        nxt_t = nn;
        i++;
    }
    asm volatile("cp.async.wait_group 0;\n");

    // ---- epilogue: last CTA resets coordination state for next replay ----
    __threadfence();
    if (t == 0) {
        unsigned old = atomicAdd(&d_doneB, 1u);
        if (old == (unsigned)(ncta - 1)) {
            d_ctrB = 0; d_doneA = 0; d_doneB = 0; d_flag = 0u;
        }
    }
}

// ---------------- Launch ----------------------------------------------------------
extern "C" void kernel_launch(void* const* d_in, const int* in_sizes, int n_in,
                              void* d_out, int out_size) {
    const float* x    = (const float*)d_in[0];
    const float* cv1w = (const float*)d_in[1];
    const float* cv1b = (const float*)d_in[2];
    // d_in[3], d_in[4] = ch_cv2_w/b : mathematically unused (softmax over size-1 dim)
    const float* cv3w = (const float*)d_in[5];
    const float* cv3b = (const float*)d_in[6];
    const float* lng  = (const float*)d_in[7];
    const float* lnb  = (const float*)d_in[8];
    const float* sp1w = (const float*)d_in[9];
    const float* sp1b = (const float*)d_in[10];
    const float* sp2w = (const float*)d_in[11];
    const float* sp2b = (const float*)d_in[12];

    int nsm = 148;
    cudaDeviceGetAttribute(&nsm, cudaDevAttrMultiProcessorCount, 0);
    int ncta = nsm * 3;                 // 3 CTAs/SM, all co-resident
    if (ncta > MAXCTA) ncta = MAXCTA;
    const int Q = (TOT4 + ncta - 1) / ncta;   // flat float4s per CTA (<= 65536)

    const int smem_bytes = (2 * TILE_F + C + C + 256 + TP) * (int)sizeof(float);
    cudaFuncSetAttribute(psa_one, cudaFuncAttributeMaxDynamicSharedMemorySize, smem_bytes);
    psa_one<<<ncta, 256, smem_bytes>>>((const float4*)x, (float4*)d_out, ncta, Q,
                                       cv1w, cv1b, cv3w, cv3b, lng, lnb,
                                       sp1w, sp1b, sp2w, sp2b);
}

// round 17
// speedup vs baseline: 1.1363x; 1.1363x over previous
#include <cuda_runtime.h>

#define C    256
#define CH   128
#define HWn  262144
#define HW4  65536
#define SEGS 16
#define SEG_F4 4096   // HW4 / SEGS
#define EPS  1e-5f

// k3 tiling: 32 pixels per tile, depth-2 cp.async pipeline, 3 CTAs/SM, work-stealing
#define TP     32
#define TP4    8
#define TILE_F  (C * TP)       // 8192 floats = 32 KB
#define NTILES  (HWn / TP)     // 8192 tiles

__device__ float d_partials[C * SEGS];
__device__ float d_g[C];
__device__ float d_v[C];
__device__ float d_b0;
__device__ unsigned d_k1done;   // zero at load; reset by last k1 CTA each call
__device__ int d_tilectr;       // reset by last k1 CTA each call

// ---------------- Kernel 1: channel sums + (last CTA) all the tiny algebra --------
__global__ void k1_sums(const float4* __restrict__ x4,
                        const float* __restrict__ cv1w, const float* __restrict__ cv1b,
                        const float* __restrict__ cv3w, const float* __restrict__ cv3b,
                        const float* __restrict__ lng,  const float* __restrict__ lnb,
                        const float* __restrict__ sp1w, const float* __restrict__ sp1b,
                        const float* __restrict__ sp2w, const float* __restrict__ sp2b) {
    const int c = blockIdx.y, seg = blockIdx.x, t = threadIdx.x;
    const float4* xc = x4 + (size_t)c * HW4 + (size_t)seg * SEG_F4;
    float s = 0.f;
#pragma unroll
    for (int j = 0; j < 16; j++) {
        float4 u = xc[t + j * 256];
        s += (u.x + u.y) + (u.z + u.w);
    }
    __shared__ float red[256];
    red[t] = s;
    __syncthreads();
    for (int off = 128; off > 0; off >>= 1) {
        if (t < off) red[t] += red[t + off];
        __syncthreads();
    }
    if (t == 0) d_partials[c * SEGS + seg] = red[0];

    // ---- last-CTA detection ----
    __shared__ unsigned slast;
    if (t == 0) {
        __threadfence();
        unsigned old = atomicAdd(&d_k1done, 1u);
        slast = (old == (unsigned)(SEGS * C - 1)) ? 1u : 0u;
        if (slast) __threadfence();
    }
    __syncthreads();
    if (!slast) return;

    // ---- scalar algebra (exactly the former k2, this CTA only) ----
    if (t == 0) { d_k1done = 0u; d_tilectr = 0; }   // reset for next replay / k3

    __shared__ float S[C];
    __shared__ float l1[C];     // ybuf in [0,CH), s2pre/wsm in [CH,2CH)
    {
        float ss = 0.f;
#pragma unroll
        for (int j = 0; j < SEGS; j++) ss += d_partials[t * SEGS + j];
        S[t] = ss;
    }
    __syncthreads();

    if (t < CH) {
        float a = 0.f;
        for (int cc = 0; cc < C; cc++) a += cv1w[t * C + cc] * S[cc];
        l1[t] = a + (float)HWn * cv1b[t];
    } else {
        const int u = t - CH;
        float a = 0.f;
        for (int cc = 0; cc < C; cc++) a += sp2w[u * C + cc] * S[cc];
        l1[t] = a * (1.f / (float)HWn) + sp2b[u];
    }
    __syncthreads();

    float zv = cv3b[t];
    for (int cc = 0; cc < CH; cc++) zv += cv3w[t * CH + cc] * l1[cc];

    red[t] = zv;
    __syncthreads();
    for (int off = 128; off > 0; off >>= 1) {
        if (t < off) red[t] += red[t + off];
        __syncthreads();
    }
    const float mu = red[0] * (1.f / (float)C);
    __syncthreads();
    red[t] = zv * zv;
    __syncthreads();
    for (int off = 128; off > 0; off >>= 1) {
        if (t < off) red[t] += red[t + off];
        __syncthreads();
    }
    const float var = red[0] * (1.f / (float)C) - mu * mu;
    __syncthreads();

    const float zn = (zv - mu) * rsqrtf(var + EPS) * lng[t] + lnb[t];
    d_g[t] = 1.f / (1.f + expf(-zn));

    red[t] = (t < CH) ? l1[CH + t] : -1e30f;
    __syncthreads();
    for (int off = 128; off > 0; off >>= 1) {
        if (t < off) red[t] = fmaxf(red[t], red[t + off]);
        __syncthreads();
    }
    const float mx = red[0];
    __syncthreads();
    red[t] = (t < CH) ? expf(l1[CH + t] - mx) : 0.f;
    __syncthreads();
    for (int off = 128; off > 0; off >>= 1) {
        if (t < off) red[t] += red[t + off];
        __syncthreads();
    }
    const float denom = red[0];
    __syncthreads();
    if (t < CH) l1[CH + t] = expf(l1[CH + t] - mx) / denom;   // wsm
    __syncthreads();

    {
        float vv = 0.f;
        for (int c_ = 0; c_ < CH; c_++) vv += l1[CH + c_] * sp1w[c_ * C + t];
        d_v[t] = vv;
    }
    if (t == 0) {
        float bb = 0.f;
        for (int c_ = 0; c_ < CH; c_++) bb += l1[CH + c_] * sp1b[c_];
        d_b0 = bb;
    }
}

// ---------------- Kernel 3: pipelined fused yb + output (wt stores) ---------------
__device__ __forceinline__ void k3_prefetch(const float4* __restrict__ x4,
                                            float* buf, int tile, int t) {
    if (tile < NTILES) {
        unsigned dst_base = (unsigned)__cvta_generic_to_shared(buf);
        const int base4 = tile * TP4;
#pragma unroll
        for (int j = 0; j < 8; j++) {
            int i4 = t + j * 256;
            int c = i4 >> 3, p4 = i4 & 7;
            const float4* src = x4 + (size_t)c * HW4 + base4 + p4;
            unsigned dst = dst_base + i4 * 16;
            asm volatile("cp.async.cg.shared.global [%0], [%1], 16;\n" :: "r"(dst), "l"(src));
        }
    }
    asm volatile("cp.async.commit_group;\n");   // empty group OK when out of range
}

__global__ __launch_bounds__(256, 3)
void k3_out(const float4* __restrict__ x4, float4* __restrict__ out4) {
    extern __shared__ float sm[];
    float* buf0 = sm;                    // TILE_F
    float* buf1 = sm + TILE_F;           // TILE_F
    float* sv   = sm + 2 * TILE_F;       // C
    float* sg   = sv + C;                // C
    float* part = sg + C;                // 256
    float* sy   = part + 256;            // TP
    __shared__ int ssteal[3];

    const int t = threadIdx.x;
    sv[t] = d_v[t];
    sg[t] = d_g[t];
    const float b0 = d_b0;

    if (t == 0) {
        ssteal[0] = atomicAdd(&d_tilectr, 1);
        ssteal[1] = atomicAdd(&d_tilectr, 1);
    }
    __syncthreads();
    int cur_t = ssteal[0], nxt_t = ssteal[1];
    k3_prefetch(x4, buf0, cur_t, t);
    k3_prefetch(x4, buf1, nxt_t, t);

    int i = 0;
    while (cur_t < NTILES) {
        float* cur = (i & 1) ? buf1 : buf0;
        float4* cur4 = (float4*)cur;

        if (t == 0) ssteal[2] = atomicAdd(&d_tilectr, 1);   // latency hidden by wait
        asm volatile("cp.async.wait_group 1;\n");           // current tile landed
        __syncthreads();                                    // publishes ssteal[2] too
        const int nn = ssteal[2];

        // yb partial dots: p = pixel (0..31), q = channel octant (0..7)
        {
            const int p = t & 31, q = t >> 5;
            float acc = 0.f;
            const float* tp_ = cur + (q * 32) * TP + p;
            const float* vp  = sv + q * 32;
#pragma unroll
            for (int c = 0; c < 32; c++) acc += vp[c] * tp_[c * TP];
            part[q * TP + p] = acc;
        }
        __syncthreads();
        if (t < TP) {
            float yb = b0;
#pragma unroll
            for (int q = 0; q < 8; q++) yb += part[q * TP + t];
            sy[t] = 1.f / (1.f + expf(-yb));
        }
        __syncthreads();

        // out = (g[c] + sigmoid(yb[p])) * x  ; write-through stores (no L2 allocate)
        const int base4 = cur_t * TP4;
#pragma unroll
        for (int j = 0; j < 8; j++) {
            int i4 = t + j * 256;
            int c = i4 >> 3, p4 = i4 & 7;
            float4 xv = cur4[i4];
            const float gv = sg[c];
            const int p = p4 * 4;
            float4 o;
            o.x = (gv + sy[p + 0]) * xv.x;
            o.y = (gv + sy[p + 1]) * xv.y;
            o.z = (gv + sy[p + 2]) * xv.z;
            o.w = (gv + sy[p + 3]) * xv.w;
            float4* dst = out4 + (size_t)c * HW4 + base4 + p4;
            asm volatile("st.global.wt.v4.f32 [%0], {%1, %2, %3, %4};\n"
                         :: "l"(dst), "f"(o.x), "f"(o.y), "f"(o.z), "f"(o.w));
        }
        __syncthreads();                 // cur consumed
        k3_prefetch(x4, cur, nn, t);     // refill cur with stolen tile
        cur_t = nxt_t;
        nxt_t = nn;
        i++;
    }
    asm volatile("cp.async.wait_group 0;\n");   // drain before exit
}

// ---------------- Launch ----------------------------------------------------------
extern "C" void kernel_launch(void* const* d_in, const int* in_sizes, int n_in,
                              void* d_out, int out_size) {
    const float* x    = (const float*)d_in[0];
    const float* cv1w = (const float*)d_in[1];
    const float* cv1b = (const float*)d_in[2];
    // d_in[3], d_in[4] = ch_cv2_w/b : mathematically unused (softmax over size-1 dim)
    const float* cv3w = (const float*)d_in[5];
    const float* cv3b = (const float*)d_in[6];
    const float* lng  = (const float*)d_in[7];
    const float* lnb  = (const float*)d_in[8];
    const float* sp1w = (const float*)d_in[9];
    const float* sp1b = (const float*)d_in[10];
    const float* sp2w = (const float*)d_in[11];
    const float* sp2b = (const float*)d_in[12];

    int nsm = 148;
    cudaDeviceGetAttribute(&nsm, cudaDevAttrMultiProcessorCount, 0);
    const int grid3 = nsm * 3;   // 3 CTAs/SM

    dim3 g1(SEGS, C);
    k1_sums<<<g1, 256>>>((const float4*)x, cv1w, cv1b, cv3w, cv3b, lng, lnb,
                         sp1w, sp1b, sp2w, sp2b);

    const int smem_bytes = (2 * TILE_F + C + C + 256 + TP) * (int)sizeof(float);
    cudaFuncSetAttribute(k3_out, cudaFuncAttributeMaxDynamicSharedMemorySize, smem_bytes);
    k3_out<<<grid3, 256, smem_bytes>>>((const float4*)x, (float4*)d_out);
}